// round 5
// baseline (speedup 1.0000x reference)
#include <cuda_runtime.h>
#include <cstdint>
#include <cstddef>

#define BB 128
#define NN 400
#define FF 128
#define KNN 5
#define BN (BB * NN)   // 51200

// ---------------- device scratch ----------------
__device__ float g_sq[BN];
__device__ unsigned int g_Abits[(size_t)BN * 16];  // 400-bit adjacency rows, 3.3MB
__device__ float g_m[(size_t)BN * FF];
__device__ float g_h[(size_t)BN * FF];

// ---------------- squared norms ----------------
__global__ void sq_kernel(const float* __restrict__ x) {
    int row = blockIdx.x * 4 + (threadIdx.x >> 5);
    int lane = threadIdx.x & 31;
    float4 v = *(const float4*)(x + (size_t)row * FF + lane * 4);
    float s = v.x * v.x + v.y * v.y + v.z * v.z + v.w * v.w;
#pragma unroll
    for (int o = 16; o; o >>= 1) s += __shfl_xor_sync(0xffffffffu, s, o);
    if (lane == 0) g_sq[row] = s;
}

// ---------------- fused distance + top-5 + adjacency scatter ----------------
#define KNN_SMEM ((128 * 64 + 128 * 128 + 416 + 64 * 5 * 2 + 8 * 5 * 2) * 4)

__global__ void __launch_bounds__(256, 2) knn_kernel(const float* __restrict__ x) {
    extern __shared__ float sm[];
    float* s_xiT = sm;                      // 128k x 64 rows (k-major, swizzled &15)
    float* s_xjT = s_xiT + 128 * 64;        // 128k x 128 rows (swizzled &31)
    float* s_sq  = s_xjT + 128 * 128;       // 416
    float* s_bv  = s_sq + 416;              // 64 x 5 running top-5 values (sorted)
    int*   s_bi  = (int*)(s_bv + 64 * 5);   // 64 x 5 running top-5 indices
    float* s_tv  = (float*)(s_bi + 64 * 5); // 8 x 5 per-warp tile scratch
    int*   s_ti  = (int*)(s_tv + 8 * 5);    // 8 x 5

    const int b  = blockIdx.y;
    const int i0 = blockIdx.x * 64;
    const int t  = threadIdx.x;
    const int tx = t & 31, ty = t >> 5;
    const int lane = t & 31;
    const float INF = __int_as_float(0x7f800000);
    const float* xb = x + (size_t)b * NN * FF;

    for (int j = t; j < NN; j += 256) s_sq[j] = g_sq[b * NN + j];
    for (int q = t; q < 64 * KNN; q += 256) { s_bv[q] = INF; s_bi[q] = 0x7fffffff; }

    // load xi tile: 64 rows x 128 k, k-major, swizzle &15
    for (int idx = t; idx < 512; idx += 256) {
        int ob = idx >> 5, kc = idx & 31;
        float vv[4][4];
#pragma unroll
        for (int r = 0; r < 4; r++) {
            int ir = i0 + ob * 4 + r;
            float4 v = (ir < NN) ? *(const float4*)(xb + (size_t)ir * FF + kc * 4)
                                 : make_float4(0.f, 0.f, 0.f, 0.f);
            vv[r][0] = v.x; vv[r][1] = v.y; vv[r][2] = v.z; vv[r][3] = v.w;
        }
#pragma unroll
        for (int c = 0; c < 4; c++)
            *(float4*)&s_xiT[(kc * 4 + c) * 64 + (((ob ^ kc) & 15) << 2)] =
                make_float4(vv[0][c], vv[1][c], vv[2][c], vv[3][c]);
    }

    for (int j0 = 0; j0 < NN; j0 += 128) {
        __syncthreads();
        // load xj tile: 128 rows x 128 k
        for (int idx = t; idx < 1024; idx += 256) {
            int ob = idx >> 5, kc = idx & 31;
            float vv[4][4];
#pragma unroll
            for (int r = 0; r < 4; r++) {
                int jr = j0 + ob * 4 + r;
                float4 v = (jr < NN) ? *(const float4*)(xb + (size_t)jr * FF + kc * 4)
                                     : make_float4(0.f, 0.f, 0.f, 0.f);
                vv[r][0] = v.x; vv[r][1] = v.y; vv[r][2] = v.z; vv[r][3] = v.w;
            }
#pragma unroll
            for (int c = 0; c < 4; c++)
                *(float4*)&s_xjT[(kc * 4 + c) * 128 + (((ob ^ kc) & 31) << 2)] =
                    make_float4(vv[0][c], vv[1][c], vv[2][c], vv[3][c]);
        }
        __syncthreads();

        float acc[8][4] = {};
#pragma unroll
        for (int k4 = 0; k4 < 32; k4++) {
            const float* a0p = &s_xiT[(k4 * 4) * 64 + ((((2 * ty)     ^ k4) & 15) << 2)];
            const float* a1p = &s_xiT[(k4 * 4) * 64 + ((((2 * ty + 1) ^ k4) & 15) << 2)];
            const float* bbp = &s_xjT[(k4 * 4) * 128 + (((tx ^ k4) & 31) << 2)];
#pragma unroll
            for (int kk = 0; kk < 4; kk++) {
                float4 a0 = *(const float4*)(a0p + kk * 64);
                float4 a1 = *(const float4*)(a1p + kk * 64);
                float4 bj = *(const float4*)(bbp + kk * 128);
                acc[0][0] += a0.x * bj.x; acc[0][1] += a0.x * bj.y; acc[0][2] += a0.x * bj.z; acc[0][3] += a0.x * bj.w;
                acc[1][0] += a0.y * bj.x; acc[1][1] += a0.y * bj.y; acc[1][2] += a0.y * bj.z; acc[1][3] += a0.y * bj.w;
                acc[2][0] += a0.z * bj.x; acc[2][1] += a0.z * bj.y; acc[2][2] += a0.z * bj.z; acc[2][3] += a0.z * bj.w;
                acc[3][0] += a0.w * bj.x; acc[3][1] += a0.w * bj.y; acc[3][2] += a0.w * bj.z; acc[3][3] += a0.w * bj.w;
                acc[4][0] += a1.x * bj.x; acc[4][1] += a1.x * bj.y; acc[4][2] += a1.x * bj.z; acc[4][3] += a1.x * bj.w;
                acc[5][0] += a1.y * bj.x; acc[5][1] += a1.y * bj.y; acc[5][2] += a1.y * bj.z; acc[5][3] += a1.y * bj.w;
                acc[6][0] += a1.z * bj.x; acc[6][1] += a1.z * bj.y; acc[6][2] += a1.z * bj.z; acc[6][3] += a1.z * bj.w;
                acc[7][0] += a1.w * bj.x; acc[7][1] += a1.w * bj.y; acc[7][2] += a1.w * bj.z; acc[7][3] += a1.w * bj.w;
            }
        }

        // scores: row i0+ty*8+rr, col j0+tx*4+c
        float scv[8][4];
#pragma unroll
        for (int rr = 0; rr < 8; rr++)
#pragma unroll
            for (int c = 0; c < 4; c++) {
                int jg = j0 + tx * 4 + c;
                scv[rr][c] = (jg < NN) ? s_sq[jg] - 2.f * acc[rr][c] : INF;
            }

        // per-row top-5 of tile with early exit vs running 5th-best
#pragma unroll
        for (int rr = 0; rr < 8; rr++) {
            int li = ty * 8 + rr;
            int irow = i0 + li;                  // warp-uniform
            if (irow < NN) {
                float kv = s_bv[li * KNN + 4];
                int   ki = s_bi[li * KNN + 4];
                bool cand = false;
#pragma unroll
                for (int c = 0; c < 4; c++) {
                    float v = scv[rr][c];
                    int jg = j0 + tx * 4 + c;
                    cand |= (v < kv) || (v == kv && jg < ki);
                }
                if (__ballot_sync(0xffffffffu, cand)) {
                    if (lane < KNN) { s_tv[ty * KNN + lane] = INF; s_ti[ty * KNN + lane] = 0x7fffffff; }
                    __syncwarp();
                    for (int q = 0; q < KNN; q++) {
                        float bv = scv[rr][0]; int bc = 0;
                        if (scv[rr][1] < bv) { bv = scv[rr][1]; bc = 1; }
                        if (scv[rr][2] < bv) { bv = scv[rr][2]; bc = 2; }
                        if (scv[rr][3] < bv) { bv = scv[rr][3]; bc = 3; }
                        int bj = j0 + tx * 4 + bc;
#pragma unroll
                        for (int o = 16; o; o >>= 1) {
                            float ov = __shfl_xor_sync(0xffffffffu, bv, o);
                            int   oj = __shfl_xor_sync(0xffffffffu, bj, o);
                            if (ov < bv || (ov == bv && oj < bj)) { bv = ov; bj = oj; }
                        }
                        bool beats = (bv < kv) || (bv == kv && bj < ki);   // uniform
                        if (!beats) break;
                        if (lane == 0) { s_tv[ty * KNN + q] = bv; s_ti[ty * KNN + q] = bj; }
                        int lc = bj - j0 - tx * 4;
                        if (lc == 0) scv[rr][0] = INF;
                        if (lc == 1) scv[rr][1] = INF;
                        if (lc == 2) scv[rr][2] = INF;
                        if (lc == 3) scv[rr][3] = INF;
                    }
                    __syncwarp();
                    if (lane == 0) {
                        float rv[KNN]; int ri[KNN];
                        float* av = &s_bv[li * KNN]; int* ai = &s_bi[li * KNN];
                        float* tv = &s_tv[ty * KNN]; int* ti = &s_ti[ty * KNN];
                        int p = 0, q = 0;
#pragma unroll
                        for (int o = 0; o < KNN; o++) {
                            float va = av[p], vt = tv[q];
                            bool takeA = (va < vt) || (va == vt && ai[p] < ti[q]);
                            if (takeA) { rv[o] = va; ri[o] = ai[p]; p++; }
                            else       { rv[o] = vt; ri[o] = ti[q]; q++; }
                        }
#pragma unroll
                        for (int o = 0; o < KNN; o++) { av[o] = rv[o]; ai[o] = ri[o]; }
                    }
                    __syncwarp();
                }
            }
        }
    }
    __syncthreads();

    // scatter symmetric adjacency bits
    if (t < 64) {
        int il = i0 + t;
        if (il < NN) {
            size_t gi = (size_t)(b * NN + il);
#pragma unroll
            for (int q = 0; q < KNN; q++) {
                int j = s_bi[t * KNN + q];
                atomicOr(&g_Abits[gi * 16 + (j >> 5)], 1u << (j & 31));
                atomicOr(&g_Abits[((size_t)(b * NN + j)) * 16 + (il >> 5)], 1u << (il & 31));
            }
        }
    }
}

// ---------------- mean aggregation: 1 warp per node, bitmask scan ----------------
__global__ void agg_kernel(const float* __restrict__ src, float* __restrict__ dst) {
    __shared__ short s_list[4][NN];
    int w = threadIdx.x >> 5, lane = threadIdx.x & 31;
    int node = blockIdx.x * 4 + w;
    int b = node / NN;
    const unsigned int* Arow = g_Abits + (size_t)node * 16;
    unsigned int m = (lane < 13) ? Arow[lane] : 0u;
    int c = __popc(m);
    int s = c;
#pragma unroll
    for (int o = 1; o < 32; o <<= 1) {
        int v = __shfl_up_sync(0xffffffffu, s, o);
        if (lane >= o) s += v;
    }
    int base = s - c;
    int total = __shfl_sync(0xffffffffu, s, 31);
    unsigned int mm = m; int kpos = 0;
    while (mm) {
        int bit = __ffs(mm) - 1;
        s_list[w][base + kpos] = (short)(lane * 32 + bit);
        kpos++; mm &= mm - 1;
    }
    __syncwarp();
    const float* sb = src + (size_t)b * NN * FF;
    float4 acc = make_float4(0.f, 0.f, 0.f, 0.f);
    for (int e = 0; e < total; e++) {
        float4 v = *(const float4*)(sb + (size_t)s_list[w][e] * FF + lane * 4);
        acc.x += v.x; acc.y += v.y; acc.z += v.z; acc.w += v.w;
    }
    float d = (float)total;
    float4 o = make_float4(acc.x / d, acc.y / d, acc.z / d, acc.w / d);
    *(float4*)(dst + (size_t)node * FF + lane * 4) = o;
}

// ---------------- fused dual-GEMM: out = act( Xa@Wa^T + Xb@Wb^T + bias ) ----------------
#define GEMM_SMEM ((64 * 128 + 64 * 128) * 4)

template <bool RELU>
__global__ void __launch_bounds__(256, 2) gemm_kernel(
        const float* __restrict__ Xa, const float* __restrict__ Wa,
        const float* __restrict__ Xb, const float* __restrict__ Wb,
        const float* __restrict__ bias, float* __restrict__ out) {
    extern __shared__ float sm2[];
    float* s_A = sm2;              // 64k x 128 rows (k-major, swizzled &31)
    float* s_B = sm2 + 64 * 128;   // 64k x 128 cols
    const int r0 = blockIdx.x * 128;
    const int t  = threadIdx.x;
    const int tx = t & 31, ty = t >> 5;    // cols tx*4, rows ty*16..+15
    float acc[16][4] = {};

#pragma unroll
    for (int ch = 0; ch < 4; ch++) {
        const float* X = (ch < 2) ? Xa : Xb;
        const float* W = (ch < 2) ? Wa : Wb;
        const int koff = (ch & 1) * 64;
        if (ch) __syncthreads();
        // load X chunk: 128 rows x 64 k
#pragma unroll
        for (int idx0 = 0; idx0 < 512; idx0 += 256) {
            int idx = idx0 + t;
            int ob = idx >> 4, kc = idx & 15;
            float vv[4][4];
#pragma unroll
            for (int r = 0; r < 4; r++) {
                float4 v = *(const float4*)(X + (size_t)(r0 + ob * 4 + r) * FF + koff + kc * 4);
                vv[r][0] = v.x; vv[r][1] = v.y; vv[r][2] = v.z; vv[r][3] = v.w;
            }
#pragma unroll
            for (int c = 0; c < 4; c++)
                *(float4*)&s_A[(kc * 4 + c) * 128 + (((ob ^ kc) & 31) << 2)] =
                    make_float4(vv[0][c], vv[1][c], vv[2][c], vv[3][c]);
        }
        // load W chunk: 128 out-cols x 64 k
#pragma unroll
        for (int idx0 = 0; idx0 < 512; idx0 += 256) {
            int idx = idx0 + t;
            int ob = idx >> 4, kc = idx & 15;
            float vv[4][4];
#pragma unroll
            for (int r = 0; r < 4; r++) {
                float4 v = *(const float4*)(W + (size_t)(ob * 4 + r) * FF + koff + kc * 4);
                vv[r][0] = v.x; vv[r][1] = v.y; vv[r][2] = v.z; vv[r][3] = v.w;
            }
#pragma unroll
            for (int c = 0; c < 4; c++)
                *(float4*)&s_B[(kc * 4 + c) * 128 + (((ob ^ kc) & 31) << 2)] =
                    make_float4(vv[0][c], vv[1][c], vv[2][c], vv[3][c]);
        }
        __syncthreads();

#pragma unroll
        for (int k4 = 0; k4 < 16; k4++) {
            const float* bbp = &s_B[(k4 * 4) * 128 + (((tx ^ k4) & 31) << 2)];
            const float* a0p = &s_A[(k4 * 4) * 128 + ((((4 * ty + 0) ^ k4) & 31) << 2)];
            const float* a1p = &s_A[(k4 * 4) * 128 + ((((4 * ty + 1) ^ k4) & 31) << 2)];
            const float* a2p = &s_A[(k4 * 4) * 128 + ((((4 * ty + 2) ^ k4) & 31) << 2)];
            const float* a3p = &s_A[(k4 * 4) * 128 + ((((4 * ty + 3) ^ k4) & 31) << 2)];
#pragma unroll
            for (int kk = 0; kk < 4; kk++) {
                float4 bv = *(const float4*)(bbp + kk * 128);
                float4 a0 = *(const float4*)(a0p + kk * 128);
                float4 a1 = *(const float4*)(a1p + kk * 128);
                float4 a2 = *(const float4*)(a2p + kk * 128);
                float4 a3 = *(const float4*)(a3p + kk * 128);
                acc[0][0] += a0.x * bv.x;  acc[0][1] += a0.x * bv.y;  acc[0][2] += a0.x * bv.z;  acc[0][3] += a0.x * bv.w;
                acc[1][0] += a0.y * bv.x;  acc[1][1] += a0.y * bv.y;  acc[1][2] += a0.y * bv.z;  acc[1][3] += a0.y * bv.w;
                acc[2][0] += a0.z * bv.x;  acc[2][1] += a0.z * bv.y;  acc[2][2] += a0.z * bv.z;  acc[2][3] += a0.z * bv.w;
                acc[3][0] += a0.w * bv.x;  acc[3][1] += a0.w * bv.y;  acc[3][2] += a0.w * bv.z;  acc[3][3] += a0.w * bv.w;
                acc[4][0] += a1.x * bv.x;  acc[4][1] += a1.x * bv.y;  acc[4][2] += a1.x * bv.z;  acc[4][3] += a1.x * bv.w;
                acc[5][0] += a1.y * bv.x;  acc[5][1] += a1.y * bv.y;  acc[5][2] += a1.y * bv.z;  acc[5][3] += a1.y * bv.w;
                acc[6][0] += a1.z * bv.x;  acc[6][1] += a1.z * bv.y;  acc[6][2] += a1.z * bv.z;  acc[6][3] += a1.z * bv.w;
                acc[7][0] += a1.w * bv.x;  acc[7][1] += a1.w * bv.y;  acc[7][2] += a1.w * bv.z;  acc[7][3] += a1.w * bv.w;
                acc[8][0] += a2.x * bv.x;  acc[8][1] += a2.x * bv.y;  acc[8][2] += a2.x * bv.z;  acc[8][3] += a2.x * bv.w;
                acc[9][0] += a2.y * bv.x;  acc[9][1] += a2.y * bv.y;  acc[9][2] += a2.y * bv.z;  acc[9][3] += a2.y * bv.w;
                acc[10][0] += a2.z * bv.x; acc[10][1] += a2.z * bv.y; acc[10][2] += a2.z * bv.z; acc[10][3] += a2.z * bv.w;
                acc[11][0] += a2.w * bv.x; acc[11][1] += a2.w * bv.y; acc[11][2] += a2.w * bv.z; acc[11][3] += a2.w * bv.w;
                acc[12][0] += a3.x * bv.x; acc[12][1] += a3.x * bv.y; acc[12][2] += a3.x * bv.z; acc[12][3] += a3.x * bv.w;
                acc[13][0] += a3.y * bv.x; acc[13][1] += a3.y * bv.y; acc[13][2] += a3.y * bv.z; acc[13][3] += a3.y * bv.w;
                acc[14][0] += a3.z * bv.x; acc[14][1] += a3.z * bv.y; acc[14][2] += a3.z * bv.z; acc[14][3] += a3.z * bv.w;
                acc[15][0] += a3.w * bv.x; acc[15][1] += a3.w * bv.y; acc[15][2] += a3.w * bv.z; acc[15][3] += a3.w * bv.w;
            }
        }
    }

    float4 bv4 = *(const float4*)(bias + tx * 4);
    float bb4[4] = {bv4.x, bv4.y, bv4.z, bv4.w};
#pragma unroll
    for (int rr = 0; rr < 16; rr++) {
        int row = r0 + ty * 16 + rr;
        float4 o4;
        float* op = (float*)&o4;
#pragma unroll
        for (int c = 0; c < 4; c++) {
            float v = acc[rr][c] + bb4[c];
            if (RELU) v = fmaxf(v, 0.f);
            op[c] = v;
        }
        *(float4*)(out + (size_t)row * FF + tx * 4) = o4;
    }
}

// ---------------- launch ----------------
extern "C" void kernel_launch(void* const* d_in, const int* in_sizes, int n_in,
                              void* d_out, int out_size) {
    const float* x   = (const float*)d_in[0];
    const float* W1l = (const float*)d_in[1];
    const float* b1l = (const float*)d_in[2];
    const float* W1r = (const float*)d_in[3];
    const float* W2l = (const float*)d_in[4];
    const float* b2l = (const float*)d_in[5];
    const float* W2r = (const float*)d_in[6];
    float* out = (float*)d_out;

    void* aptr = nullptr;
    cudaGetSymbolAddress(&aptr, g_Abits);
    float* mp = nullptr; cudaGetSymbolAddress((void**)&mp, g_m);
    float* hp = nullptr; cudaGetSymbolAddress((void**)&hp, g_h);

    cudaFuncSetAttribute(knn_kernel, cudaFuncAttributeMaxDynamicSharedMemorySize, KNN_SMEM);
    cudaFuncSetAttribute(gemm_kernel<true>,  cudaFuncAttributeMaxDynamicSharedMemorySize, GEMM_SMEM);
    cudaFuncSetAttribute(gemm_kernel<false>, cudaFuncAttributeMaxDynamicSharedMemorySize, GEMM_SMEM);

    cudaMemsetAsync(aptr, 0, (size_t)BN * 16 * sizeof(unsigned int), 0);
    sq_kernel<<<BN / 4, 128>>>(x);
    dim3 kg(7, BB);
    knn_kernel<<<kg, 256, KNN_SMEM>>>(x);
    agg_kernel<<<BN / 4, 128>>>(x, mp);
    gemm_kernel<true><<<BN / 128, 256, GEMM_SMEM>>>(mp, W1l, x, W1r, b1l, hp);
    agg_kernel<<<BN / 4, 128>>>(hp, mp);
    gemm_kernel<false><<<BN / 128, 256, GEMM_SMEM>>>(mp, W2l, hp, W2r, b2l, out);
}

// round 6
// speedup vs baseline: 1.5144x; 1.5144x over previous
#include <cuda_runtime.h>
#include <cstdint>
#include <cstddef>

#define BB 128
#define NN 400
#define FF 128
#define KNN 5
#define BN (BB * NN)   // 51200

// ---------------- device scratch ----------------
__device__ float g_sq[BN];
__device__ unsigned int g_Abits[(size_t)BN * 16];  // 400-bit adjacency rows, 3.3MB
__device__ float g_m[(size_t)BN * FF];
__device__ float g_h[(size_t)BN * FF];

// ---------------- squared norms ----------------
__global__ void sq_kernel(const float* __restrict__ x) {
    int row = blockIdx.x * 4 + (threadIdx.x >> 5);
    int lane = threadIdx.x & 31;
    float4 v = *(const float4*)(x + (size_t)row * FF + lane * 4);
    float s = v.x * v.x + v.y * v.y + v.z * v.z + v.w * v.w;
#pragma unroll
    for (int o = 16; o; o >>= 1) s += __shfl_xor_sync(0xffffffffu, s, o);
    if (lane == 0) g_sq[row] = s;
}

// ---------------- fused distance + top-5 + adjacency scatter ----------------
// 64 i-rows per block, j-tiles of 128, 8x4 thread tile, scores in registers.
#define KNN_SMEM ((128 * 64 + 128 * 128 + 416 + 64 * 5 * 2 + 8 * 5 * 2) * 4)

__global__ void __launch_bounds__(256, 2) knn_kernel(const float* __restrict__ x) {
    extern __shared__ float sm[];
    float* s_xiT = sm;                      // 128k x 64 rows (k-major, swizzled &15)
    float* s_xjT = s_xiT + 128 * 64;        // 128k x 128 rows (swizzled &31)
    float* s_sq  = s_xjT + 128 * 128;       // 416
    float* s_bv  = s_sq + 416;              // 64 x 5 running top-5 values (sorted)
    int*   s_bi  = (int*)(s_bv + 64 * 5);   // 64 x 5 running top-5 indices
    float* s_tv  = (float*)(s_bi + 64 * 5); // 8 x 5 per-warp tile scratch
    int*   s_ti  = (int*)(s_tv + 8 * 5);    // 8 x 5

    const int b  = blockIdx.y;
    const int i0 = blockIdx.x * 64;
    const int t  = threadIdx.x;
    const int tx = t & 31, ty = t >> 5;
    const int lane = t & 31;
    const float INF = __int_as_float(0x7f800000);
    const float* xb = x + (size_t)b * NN * FF;

    for (int j = t; j < NN; j += 256) s_sq[j] = g_sq[b * NN + j];
    for (int q = t; q < 64 * KNN; q += 256) { s_bv[q] = INF; s_bi[q] = 0x7fffffff; }

    // load xi tile: 64 rows x 128 k, k-major, swizzle &15
    for (int idx = t; idx < 512; idx += 256) {
        int ob = idx >> 5, kc = idx & 31;
        float vv[4][4];
#pragma unroll
        for (int r = 0; r < 4; r++) {
            int ir = i0 + ob * 4 + r;
            float4 v = (ir < NN) ? *(const float4*)(xb + (size_t)ir * FF + kc * 4)
                                 : make_float4(0.f, 0.f, 0.f, 0.f);
            vv[r][0] = v.x; vv[r][1] = v.y; vv[r][2] = v.z; vv[r][3] = v.w;
        }
#pragma unroll
        for (int c = 0; c < 4; c++)
            *(float4*)&s_xiT[(kc * 4 + c) * 64 + (((ob ^ kc) & 15) << 2)] =
                make_float4(vv[0][c], vv[1][c], vv[2][c], vv[3][c]);
    }

    for (int j0 = 0; j0 < NN; j0 += 128) {
        __syncthreads();
        // load xj tile: 128 rows x 128 k
        for (int idx = t; idx < 1024; idx += 256) {
            int ob = idx >> 5, kc = idx & 31;
            float vv[4][4];
#pragma unroll
            for (int r = 0; r < 4; r++) {
                int jr = j0 + ob * 4 + r;
                float4 v = (jr < NN) ? *(const float4*)(xb + (size_t)jr * FF + kc * 4)
                                     : make_float4(0.f, 0.f, 0.f, 0.f);
                vv[r][0] = v.x; vv[r][1] = v.y; vv[r][2] = v.z; vv[r][3] = v.w;
            }
#pragma unroll
            for (int c = 0; c < 4; c++)
                *(float4*)&s_xjT[(kc * 4 + c) * 128 + (((ob ^ kc) & 31) << 2)] =
                    make_float4(vv[0][c], vv[1][c], vv[2][c], vv[3][c]);
        }
        __syncthreads();

        float acc[8][4] = {};
#pragma unroll 4
        for (int k = 0; k < 128; k++) {
            int sw = k >> 2;
            float4 a0 = *(const float4*)&s_xiT[k * 64  + ((((2 * ty)     ^ sw) & 15) << 2)];
            float4 a1 = *(const float4*)&s_xiT[k * 64  + ((((2 * ty + 1) ^ sw) & 15) << 2)];
            float4 bj = *(const float4*)&s_xjT[k * 128 + (((tx ^ sw) & 31) << 2)];
            acc[0][0] += a0.x * bj.x; acc[0][1] += a0.x * bj.y; acc[0][2] += a0.x * bj.z; acc[0][3] += a0.x * bj.w;
            acc[1][0] += a0.y * bj.x; acc[1][1] += a0.y * bj.y; acc[1][2] += a0.y * bj.z; acc[1][3] += a0.y * bj.w;
            acc[2][0] += a0.z * bj.x; acc[2][1] += a0.z * bj.y; acc[2][2] += a0.z * bj.z; acc[2][3] += a0.z * bj.w;
            acc[3][0] += a0.w * bj.x; acc[3][1] += a0.w * bj.y; acc[3][2] += a0.w * bj.z; acc[3][3] += a0.w * bj.w;
            acc[4][0] += a1.x * bj.x; acc[4][1] += a1.x * bj.y; acc[4][2] += a1.x * bj.z; acc[4][3] += a1.x * bj.w;
            acc[5][0] += a1.y * bj.x; acc[5][1] += a1.y * bj.y; acc[5][2] += a1.y * bj.z; acc[5][3] += a1.y * bj.w;
            acc[6][0] += a1.z * bj.x; acc[6][1] += a1.z * bj.y; acc[6][2] += a1.z * bj.z; acc[6][3] += a1.z * bj.w;
            acc[7][0] += a1.w * bj.x; acc[7][1] += a1.w * bj.y; acc[7][2] += a1.w * bj.z; acc[7][3] += a1.w * bj.w;
        }

        // scores in registers: row i0+ty*8+rr, col j0+tx*4+c
        float scv[8][4];
#pragma unroll
        for (int rr = 0; rr < 8; rr++)
#pragma unroll
            for (int c = 0; c < 4; c++) {
                int jg = j0 + tx * 4 + c;
                scv[rr][c] = (jg < NN) ? s_sq[jg] - 2.f * acc[rr][c] : INF;
            }

        // per-row top-5 of tile with exact early exit vs running 5th-best
#pragma unroll
        for (int rr = 0; rr < 8; rr++) {
            int li = ty * 8 + rr;
            int irow = i0 + li;                  // warp-uniform
            if (irow < NN) {
                float kv = s_bv[li * KNN + 4];
                int   ki = s_bi[li * KNN + 4];
                bool cand = false;
#pragma unroll
                for (int c = 0; c < 4; c++) {
                    float v = scv[rr][c];
                    int jg = j0 + tx * 4 + c;
                    cand |= (v < kv) || (v == kv && jg < ki);
                }
                if (__ballot_sync(0xffffffffu, cand)) {
                    if (lane < KNN) { s_tv[ty * KNN + lane] = INF; s_ti[ty * KNN + lane] = 0x7fffffff; }
                    __syncwarp();
                    for (int q = 0; q < KNN; q++) {
                        float bv = scv[rr][0]; int bc = 0;
                        if (scv[rr][1] < bv) { bv = scv[rr][1]; bc = 1; }
                        if (scv[rr][2] < bv) { bv = scv[rr][2]; bc = 2; }
                        if (scv[rr][3] < bv) { bv = scv[rr][3]; bc = 3; }
                        int bj = j0 + tx * 4 + bc;
#pragma unroll
                        for (int o = 16; o; o >>= 1) {
                            float ov = __shfl_xor_sync(0xffffffffu, bv, o);
                            int   oj = __shfl_xor_sync(0xffffffffu, bj, o);
                            if (ov < bv || (ov == bv && oj < bj)) { bv = ov; bj = oj; }
                        }
                        bool beats = (bv < kv) || (bv == kv && bj < ki);   // warp-uniform
                        if (!beats) break;
                        if (lane == 0) { s_tv[ty * KNN + q] = bv; s_ti[ty * KNN + q] = bj; }
                        int lc = bj - j0 - tx * 4;
                        if (lc == 0) scv[rr][0] = INF;
                        if (lc == 1) scv[rr][1] = INF;
                        if (lc == 2) scv[rr][2] = INF;
                        if (lc == 3) scv[rr][3] = INF;
                    }
                    __syncwarp();
                    if (lane == 0) {
                        float rv[KNN]; int ri[KNN];
                        float* av = &s_bv[li * KNN]; int* ai = &s_bi[li * KNN];
                        float* tv = &s_tv[ty * KNN]; int* ti = &s_ti[ty * KNN];
                        int p = 0, q = 0;
#pragma unroll
                        for (int o = 0; o < KNN; o++) {
                            float va = av[p], vt = tv[q];
                            bool takeA = (va < vt) || (va == vt && ai[p] < ti[q]);
                            if (takeA) { rv[o] = va; ri[o] = ai[p]; p++; }
                            else       { rv[o] = vt; ri[o] = ti[q]; q++; }
                        }
#pragma unroll
                        for (int o = 0; o < KNN; o++) { av[o] = rv[o]; ai[o] = ri[o]; }
                    }
                    __syncwarp();
                }
            }
        }
    }
    __syncthreads();

    // scatter symmetric adjacency bits
    if (t < 64) {
        int il = i0 + t;
        if (il < NN) {
            size_t gi = (size_t)(b * NN + il);
#pragma unroll
            for (int q = 0; q < KNN; q++) {
                int j = s_bi[t * KNN + q];
                atomicOr(&g_Abits[gi * 16 + (j >> 5)], 1u << (j & 31));
                atomicOr(&g_Abits[((size_t)(b * NN + j)) * 16 + (il >> 5)], 1u << (il & 31));
            }
        }
    }
}

// ---------------- mean aggregation: 1 warp per node, bitmask scan ----------------
__global__ void agg_kernel(const float* __restrict__ src, float* __restrict__ dst) {
    __shared__ short s_list[4][NN];
    int w = threadIdx.x >> 5, lane = threadIdx.x & 31;
    int node = blockIdx.x * 4 + w;
    int b = node / NN;
    const unsigned int* Arow = g_Abits + (size_t)node * 16;
    unsigned int m = (lane < 13) ? Arow[lane] : 0u;
    int c = __popc(m);
    int s = c;
#pragma unroll
    for (int o = 1; o < 32; o <<= 1) {
        int v = __shfl_up_sync(0xffffffffu, s, o);
        if (lane >= o) s += v;
    }
    int base = s - c;
    int total = __shfl_sync(0xffffffffu, s, 31);
    unsigned int mm = m; int kpos = 0;
    while (mm) {
        int bit = __ffs(mm) - 1;
        s_list[w][base + kpos] = (short)(lane * 32 + bit);
        kpos++; mm &= mm - 1;
    }
    __syncwarp();
    const float* sb = src + (size_t)b * NN * FF;
    float4 acc = make_float4(0.f, 0.f, 0.f, 0.f);
    for (int e = 0; e < total; e++) {
        float4 v = *(const float4*)(sb + (size_t)s_list[w][e] * FF + lane * 4);
        acc.x += v.x; acc.y += v.y; acc.z += v.z; acc.w += v.w;
    }
    float d = (float)total;
    float4 o = make_float4(acc.x / d, acc.y / d, acc.z / d, acc.w / d);
    *(float4*)(dst + (size_t)node * FF + lane * 4) = o;
}

// ---------------- fused dual-GEMM: out = act( Xa@Wa^T + Xb@Wb^T + bias ) ----------------
// 128x128 block tile, 256 threads, 16x4 thread tile, k-chunks of 64.
#define GEMM_SMEM ((64 * 128 + 64 * 128) * 4)

template <bool RELU>
__global__ void __launch_bounds__(256, 2) gemm_kernel(
        const float* __restrict__ Xa, const float* __restrict__ Wa,
        const float* __restrict__ Xb, const float* __restrict__ Wb,
        const float* __restrict__ bias, float* __restrict__ out) {
    extern __shared__ float sm2[];
    float* s_A = sm2;              // 64k x 128 rows (k-major, swizzled &31)
    float* s_B = sm2 + 64 * 128;   // 64k x 128 cols
    const int r0 = blockIdx.x * 128;
    const int t  = threadIdx.x;
    const int tx = t & 31, ty = t >> 5;    // cols tx*4, rows ty*16..+15
    float acc[16][4] = {};

#pragma unroll
    for (int ch = 0; ch < 4; ch++) {
        const float* X = (ch < 2) ? Xa : Xb;
        const float* W = (ch < 2) ? Wa : Wb;
        const int koff = (ch & 1) * 64;
        if (ch) __syncthreads();
        // load X chunk: 128 rows x 64 k
#pragma unroll
        for (int idx0 = 0; idx0 < 512; idx0 += 256) {
            int idx = idx0 + t;
            int ob = idx >> 4, kc = idx & 15;
            float vv[4][4];
#pragma unroll
            for (int r = 0; r < 4; r++) {
                float4 v = *(const float4*)(X + (size_t)(r0 + ob * 4 + r) * FF + koff + kc * 4);
                vv[r][0] = v.x; vv[r][1] = v.y; vv[r][2] = v.z; vv[r][3] = v.w;
            }
#pragma unroll
            for (int c = 0; c < 4; c++)
                *(float4*)&s_A[(kc * 4 + c) * 128 + (((ob ^ kc) & 31) << 2)] =
                    make_float4(vv[0][c], vv[1][c], vv[2][c], vv[3][c]);
        }
        // load W chunk: 128 out-cols x 64 k
#pragma unroll
        for (int idx0 = 0; idx0 < 512; idx0 += 256) {
            int idx = idx0 + t;
            int ob = idx >> 4, kc = idx & 15;
            float vv[4][4];
#pragma unroll
            for (int r = 0; r < 4; r++) {
                float4 v = *(const float4*)(W + (size_t)(ob * 4 + r) * FF + koff + kc * 4);
                vv[r][0] = v.x; vv[r][1] = v.y; vv[r][2] = v.z; vv[r][3] = v.w;
            }
#pragma unroll
            for (int c = 0; c < 4; c++)
                *(float4*)&s_B[(kc * 4 + c) * 128 + (((ob ^ kc) & 31) << 2)] =
                    make_float4(vv[0][c], vv[1][c], vv[2][c], vv[3][c]);
        }
        __syncthreads();

#pragma unroll 4
        for (int k = 0; k < 64; k++) {
            int sw = k >> 2;
            float4 bv = *(const float4*)&s_B[k * 128 + (((tx ^ sw) & 31) << 2)];
#pragma unroll
            for (int qq = 0; qq < 4; qq++) {
                float4 av = *(const float4*)&s_A[k * 128 + ((((4 * ty + qq) ^ sw) & 31) << 2)];
                acc[qq * 4 + 0][0] += av.x * bv.x; acc[qq * 4 + 0][1] += av.x * bv.y;
                acc[qq * 4 + 0][2] += av.x * bv.z; acc[qq * 4 + 0][3] += av.x * bv.w;
                acc[qq * 4 + 1][0] += av.y * bv.x; acc[qq * 4 + 1][1] += av.y * bv.y;
                acc[qq * 4 + 1][2] += av.y * bv.z; acc[qq * 4 + 1][3] += av.y * bv.w;
                acc[qq * 4 + 2][0] += av.z * bv.x; acc[qq * 4 + 2][1] += av.z * bv.y;
                acc[qq * 4 + 2][2] += av.z * bv.z; acc[qq * 4 + 2][3] += av.z * bv.w;
                acc[qq * 4 + 3][0] += av.w * bv.x; acc[qq * 4 + 3][1] += av.w * bv.y;
                acc[qq * 4 + 3][2] += av.w * bv.z; acc[qq * 4 + 3][3] += av.w * bv.w;
            }
        }
    }

    float4 bv4 = *(const float4*)(bias + tx * 4);
    float bb[4] = {bv4.x, bv4.y, bv4.z, bv4.w};
#pragma unroll
    for (int rr = 0; rr < 16; rr++) {
        int row = r0 + ty * 16 + rr;
        float4 o4;
        float* op = (float*)&o4;
#pragma unroll
        for (int c = 0; c < 4; c++) {
            float v = acc[rr][c] + bb[c];
            if (RELU) v = fmaxf(v, 0.f);
            op[c] = v;
        }
        *(float4*)(out + (size_t)row * FF + tx * 4) = o4;
    }
}

// ---------------- launch ----------------
extern "C" void kernel_launch(void* const* d_in, const int* in_sizes, int n_in,
                              void* d_out, int out_size) {
    const float* x   = (const float*)d_in[0];
    const float* W1l = (const float*)d_in[1];
    const float* b1l = (const float*)d_in[2];
    const float* W1r = (const float*)d_in[3];
    const float* W2l = (const float*)d_in[4];
    const float* b2l = (const float*)d_in[5];
    const float* W2r = (const float*)d_in[6];
    float* out = (float*)d_out;

    void* aptr = nullptr;
    cudaGetSymbolAddress(&aptr, g_Abits);
    float* mp = nullptr; cudaGetSymbolAddress((void**)&mp, g_m);
    float* hp = nullptr; cudaGetSymbolAddress((void**)&hp, g_h);

    cudaFuncSetAttribute(knn_kernel, cudaFuncAttributeMaxDynamicSharedMemorySize, KNN_SMEM);
    cudaFuncSetAttribute(gemm_kernel<true>,  cudaFuncAttributeMaxDynamicSharedMemorySize, GEMM_SMEM);
    cudaFuncSetAttribute(gemm_kernel<false>, cudaFuncAttributeMaxDynamicSharedMemorySize, GEMM_SMEM);

    cudaMemsetAsync(aptr, 0, (size_t)BN * 16 * sizeof(unsigned int), 0);
    sq_kernel<<<BN / 4, 128>>>(x);
    dim3 kg(7, BB);
    knn_kernel<<<kg, 256, KNN_SMEM>>>(x);
    agg_kernel<<<BN / 4, 128>>>(x, mp);
    gemm_kernel<true><<<BN / 128, 256, GEMM_SMEM>>>(mp, W1l, x, W1r, b1l, hp);
    agg_kernel<<<BN / 4, 128>>>(hp, mp);
    gemm_kernel<false><<<BN / 128, 256, GEMM_SMEM>>>(mp, W2l, hp, W2r, b2l, out);
}

// round 8
// speedup vs baseline: 1.6935x; 1.1183x over previous
#include <cuda_runtime.h>
#include <cuda_bf16.h>
#include <cstdint>
#include <cstddef>

#define BB 128
#define NN 400
#define FF 128
#define KNN 5
#define BN (BB * NN)   // 51200

// ---------------- device scratch ----------------
__device__ float g_sq[BN];
__device__ unsigned int g_Abits[(size_t)BN * 16];  // 400-bit adjacency rows, 3.3MB
__device__ float g_m[(size_t)BN * FF];
__device__ float g_h[(size_t)BN * FF];

// ---------------- warp-MMA helpers (base-target PTX: ldmatrix + mma.sync) ----------------
__device__ __forceinline__ uint32_t smem_u32(const void* p) {
    uint32_t a;
    asm("{ .reg .u64 t; cvta.to.shared.u64 t, %1; cvt.u32.u64 %0, t; }" : "=r"(a) : "l"(p));
    return a;
}
__device__ __forceinline__ void ldm_x4(uint32_t* r, uint32_t addr) {
    asm volatile("ldmatrix.sync.aligned.m8n8.x4.shared.b16 {%0,%1,%2,%3}, [%4];"
        : "=r"(r[0]), "=r"(r[1]), "=r"(r[2]), "=r"(r[3]) : "r"(addr));
}
__device__ __forceinline__ void mma16816(float* c, const uint32_t* a, const uint32_t* b) {
    asm volatile("mma.sync.aligned.m16n8k16.row.col.f32.bf16.bf16.f32 "
        "{%0,%1,%2,%3}, {%4,%5,%6,%7}, {%8,%9}, {%0,%1,%2,%3};"
        : "+f"(c[0]), "+f"(c[1]), "+f"(c[2]), "+f"(c[3])
        : "r"(a[0]), "r"(a[1]), "r"(a[2]), "r"(a[3]), "r"(b[0]), "r"(b[1]));
}
// bf16 tile: 128 rows x 128 cols, 256B/row, 16B-unit swizzle u' = u ^ (row&7)
__device__ __forceinline__ uint32_t toff(int row, int k) {   // k in bf16 elems
    return (uint32_t)(row * 256 + ((((k >> 3) ^ (row & 7)) << 4) | ((k & 7) << 1)));
}
__device__ __forceinline__ uint32_t pk_bf(__nv_bfloat16 a, __nv_bfloat16 b) {
    return (uint32_t)__bfloat16_as_ushort(a) | ((uint32_t)__bfloat16_as_ushort(b) << 16);
}

// ---------------- squared norms ----------------
__global__ void sq_kernel(const float* __restrict__ x) {
    int row = blockIdx.x * 4 + (threadIdx.x >> 5);
    int lane = threadIdx.x & 31;
    float4 v = *(const float4*)(x + (size_t)row * FF + lane * 4);
    float s = v.x * v.x + v.y * v.y + v.z * v.z + v.w * v.w;
#pragma unroll
    for (int o = 16; o; o >>= 1) s += __shfl_xor_sync(0xffffffffu, s, o);
    if (lane == 0) g_sq[row] = s;
}

// ---------------- fused distance + top-5 + adjacency scatter (R6, unchanged) ----------------
#define KNN_SMEM ((128 * 64 + 128 * 128 + 416 + 64 * 5 * 2 + 8 * 5 * 2) * 4)

__global__ void __launch_bounds__(256, 2) knn_kernel(const float* __restrict__ x) {
    extern __shared__ float sm[];
    float* s_xiT = sm;
    float* s_xjT = s_xiT + 128 * 64;
    float* s_sq  = s_xjT + 128 * 128;
    float* s_bv  = s_sq + 416;
    int*   s_bi  = (int*)(s_bv + 64 * 5);
    float* s_tv  = (float*)(s_bi + 64 * 5);
    int*   s_ti  = (int*)(s_tv + 8 * 5);

    const int b  = blockIdx.y;
    const int i0 = blockIdx.x * 64;
    const int t  = threadIdx.x;
    const int tx = t & 31, ty = t >> 5;
    const int lane = t & 31;
    const float INF = __int_as_float(0x7f800000);
    const float* xb = x + (size_t)b * NN * FF;

    for (int j = t; j < NN; j += 256) s_sq[j] = g_sq[b * NN + j];
    for (int q = t; q < 64 * KNN; q += 256) { s_bv[q] = INF; s_bi[q] = 0x7fffffff; }

    for (int idx = t; idx < 512; idx += 256) {
        int ob = idx >> 5, kc = idx & 31;
        float vv[4][4];
#pragma unroll
        for (int r = 0; r < 4; r++) {
            int ir = i0 + ob * 4 + r;
            float4 v = (ir < NN) ? *(const float4*)(xb + (size_t)ir * FF + kc * 4)
                                 : make_float4(0.f, 0.f, 0.f, 0.f);
            vv[r][0] = v.x; vv[r][1] = v.y; vv[r][2] = v.z; vv[r][3] = v.w;
        }
#pragma unroll
        for (int c = 0; c < 4; c++)
            *(float4*)&s_xiT[(kc * 4 + c) * 64 + (((ob ^ kc) & 15) << 2)] =
                make_float4(vv[0][c], vv[1][c], vv[2][c], vv[3][c]);
    }

    for (int j0 = 0; j0 < NN; j0 += 128) {
        __syncthreads();
        for (int idx = t; idx < 1024; idx += 256) {
            int ob = idx >> 5, kc = idx & 31;
            float vv[4][4];
#pragma unroll
            for (int r = 0; r < 4; r++) {
                int jr = j0 + ob * 4 + r;
                float4 v = (jr < NN) ? *(const float4*)(xb + (size_t)jr * FF + kc * 4)
                                     : make_float4(0.f, 0.f, 0.f, 0.f);
                vv[r][0] = v.x; vv[r][1] = v.y; vv[r][2] = v.z; vv[r][3] = v.w;
            }
#pragma unroll
            for (int c = 0; c < 4; c++)
                *(float4*)&s_xjT[(kc * 4 + c) * 128 + (((ob ^ kc) & 31) << 2)] =
                    make_float4(vv[0][c], vv[1][c], vv[2][c], vv[3][c]);
        }
        __syncthreads();

        float acc[8][4] = {};
#pragma unroll 4
        for (int k = 0; k < 128; k++) {
            int sw = k >> 2;
            float4 a0 = *(const float4*)&s_xiT[k * 64  + ((((2 * ty)     ^ sw) & 15) << 2)];
            float4 a1 = *(const float4*)&s_xiT[k * 64  + ((((2 * ty + 1) ^ sw) & 15) << 2)];
            float4 bj = *(const float4*)&s_xjT[k * 128 + (((tx ^ sw) & 31) << 2)];
            acc[0][0] += a0.x * bj.x; acc[0][1] += a0.x * bj.y; acc[0][2] += a0.x * bj.z; acc[0][3] += a0.x * bj.w;
            acc[1][0] += a0.y * bj.x; acc[1][1] += a0.y * bj.y; acc[1][2] += a0.y * bj.z; acc[1][3] += a0.y * bj.w;
            acc[2][0] += a0.z * bj.x; acc[2][1] += a0.z * bj.y; acc[2][2] += a0.z * bj.z; acc[2][3] += a0.z * bj.w;
            acc[3][0] += a0.w * bj.x; acc[3][1] += a0.w * bj.y; acc[3][2] += a0.w * bj.z; acc[3][3] += a0.w * bj.w;
            acc[4][0] += a1.x * bj.x; acc[4][1] += a1.x * bj.y; acc[4][2] += a1.x * bj.z; acc[4][3] += a1.x * bj.w;
            acc[5][0] += a1.y * bj.x; acc[5][1] += a1.y * bj.y; acc[5][2] += a1.y * bj.z; acc[5][3] += a1.y * bj.w;
            acc[6][0] += a1.z * bj.x; acc[6][1] += a1.z * bj.y; acc[6][2] += a1.z * bj.z; acc[6][3] += a1.z * bj.w;
            acc[7][0] += a1.w * bj.x; acc[7][1] += a1.w * bj.y; acc[7][2] += a1.w * bj.z; acc[7][3] += a1.w * bj.w;
        }

        float scv[8][4];
#pragma unroll
        for (int rr = 0; rr < 8; rr++)
#pragma unroll
            for (int c = 0; c < 4; c++) {
                int jg = j0 + tx * 4 + c;
                scv[rr][c] = (jg < NN) ? s_sq[jg] - 2.f * acc[rr][c] : INF;
            }

#pragma unroll
        for (int rr = 0; rr < 8; rr++) {
            int li = ty * 8 + rr;
            int irow = i0 + li;
            if (irow < NN) {
                float kv = s_bv[li * KNN + 4];
                int   ki = s_bi[li * KNN + 4];
                bool cand = false;
#pragma unroll
                for (int c = 0; c < 4; c++) {
                    float v = scv[rr][c];
                    int jg = j0 + tx * 4 + c;
                    cand |= (v < kv) || (v == kv && jg < ki);
                }
                if (__ballot_sync(0xffffffffu, cand)) {
                    if (lane < KNN) { s_tv[ty * KNN + lane] = INF; s_ti[ty * KNN + lane] = 0x7fffffff; }
                    __syncwarp();
                    for (int q = 0; q < KNN; q++) {
                        float bv = scv[rr][0]; int bc = 0;
                        if (scv[rr][1] < bv) { bv = scv[rr][1]; bc = 1; }
                        if (scv[rr][2] < bv) { bv = scv[rr][2]; bc = 2; }
                        if (scv[rr][3] < bv) { bv = scv[rr][3]; bc = 3; }
                        int bj = j0 + tx * 4 + bc;
#pragma unroll
                        for (int o = 16; o; o >>= 1) {
                            float ov = __shfl_xor_sync(0xffffffffu, bv, o);
                            int   oj = __shfl_xor_sync(0xffffffffu, bj, o);
                            if (ov < bv || (ov == bv && oj < bj)) { bv = ov; bj = oj; }
                        }
                        bool beats = (bv < kv) || (bv == kv && bj < ki);
                        if (!beats) break;
                        if (lane == 0) { s_tv[ty * KNN + q] = bv; s_ti[ty * KNN + q] = bj; }
                        int lc = bj - j0 - tx * 4;
                        if (lc == 0) scv[rr][0] = INF;
                        if (lc == 1) scv[rr][1] = INF;
                        if (lc == 2) scv[rr][2] = INF;
                        if (lc == 3) scv[rr][3] = INF;
                    }
                    __syncwarp();
                    if (lane == 0) {
                        float rv[KNN]; int ri[KNN];
                        float* av = &s_bv[li * KNN]; int* ai = &s_bi[li * KNN];
                        float* tv = &s_tv[ty * KNN]; int* ti = &s_ti[ty * KNN];
                        int p = 0, q = 0;
#pragma unroll
                        for (int o = 0; o < KNN; o++) {
                            float va = av[p], vt = tv[q];
                            bool takeA = (va < vt) || (va == vt && ai[p] < ti[q]);
                            if (takeA) { rv[o] = va; ri[o] = ai[p]; p++; }
                            else       { rv[o] = vt; ri[o] = ti[q]; q++; }
                        }
#pragma unroll
                        for (int o = 0; o < KNN; o++) { av[o] = rv[o]; ai[o] = ri[o]; }
                    }
                    __syncwarp();
                }
            }
        }
    }
    __syncthreads();

    if (t < 64) {
        int il = i0 + t;
        if (il < NN) {
            size_t gi = (size_t)(b * NN + il);
#pragma unroll
            for (int q = 0; q < KNN; q++) {
                int j = s_bi[t * KNN + q];
                atomicOr(&g_Abits[gi * 16 + (j >> 5)], 1u << (j & 31));
                atomicOr(&g_Abits[((size_t)(b * NN + j)) * 16 + (il >> 5)], 1u << (il & 31));
            }
        }
    }
}

// ---------------- mean aggregation (R6, unchanged) ----------------
__global__ void agg_kernel(const float* __restrict__ src, float* __restrict__ dst) {
    __shared__ short s_list[4][NN];
    int w = threadIdx.x >> 5, lane = threadIdx.x & 31;
    int node = blockIdx.x * 4 + w;
    int b = node / NN;
    const unsigned int* Arow = g_Abits + (size_t)node * 16;
    unsigned int m = (lane < 13) ? Arow[lane] : 0u;
    int c = __popc(m);
    int s = c;
#pragma unroll
    for (int o = 1; o < 32; o <<= 1) {
        int v = __shfl_up_sync(0xffffffffu, s, o);
        if (lane >= o) s += v;
    }
    int base = s - c;
    int total = __shfl_sync(0xffffffffu, s, 31);
    unsigned int mm = m; int kpos = 0;
    while (mm) {
        int bit = __ffs(mm) - 1;
        s_list[w][base + kpos] = (short)(lane * 32 + bit);
        kpos++; mm &= mm - 1;
    }
    __syncwarp();
    const float* sb = src + (size_t)b * NN * FF;
    float4 acc = make_float4(0.f, 0.f, 0.f, 0.f);
    for (int e = 0; e < total; e++) {
        float4 v = *(const float4*)(sb + (size_t)s_list[w][e] * FF + lane * 4);
        acc.x += v.x; acc.y += v.y; acc.z += v.z; acc.w += v.w;
    }
    float d = (float)total;
    float4 o = make_float4(acc.x / d, acc.y / d, acc.z / d, acc.w / d);
    *(float4*)(dst + (size_t)node * FF + lane * 4) = o;
}

// ---------------- warp-MMA split-bf16 dual-GEMM ----------------
// out[r0..r0+128][128] = act( Xa@Wa^T + Xb@Wb^T + bias ); 3-pass: Ah*Bh + Ah*Bl + Al*Bh
#define MMA_SMEM (4 * 32768)

template <bool RELU>
__global__ void __launch_bounds__(256) mma_gemm(
        const float* __restrict__ Xa, const float* __restrict__ Wa,
        const float* __restrict__ Xb, const float* __restrict__ Wb,
        const float* __restrict__ bias, float* __restrict__ out) {
    extern __shared__ char dsm[];
    char* sAh = dsm;             // A hi: 128x128 bf16, swizzled
    char* sAl = dsm + 32768;     // A lo
    char* sBh = dsm + 65536;     // B hi (W rows = out cols, k-contig)
    char* sBl = dsm + 98304;     // B lo
    const uint32_t aA = smem_u32(dsm);
    const uint32_t aB = aA + 65536;

    const int r0 = blockIdx.x * 128;
    const int t  = threadIdx.x;
    const int wid = t >> 5, lane = t & 31;
    const int wm = wid & 3, wn = wid >> 2;      // warp tile: rows wm*32..+31, cols wn*64..+63

    // ldmatrix lane-address bases
    const int mat = lane >> 3, mrow = lane & 7;
    const int arow = wm * 32 + ((mat & 1) << 3) + mrow;   // + mt*16
    const int aku  = mat >> 1;
    const int ar7  = arow & 7;
    const int brow = wn * 64 + ((mat >> 1) << 3) + mrow;  // + nc*16
    const int bku  = mat & 1;
    const int br7  = brow & 7;

    float c[2][8][4] = {};

    for (int src = 0; src < 2; src++) {
        const float* X = src ? Xb : Xa;
        const float* W = src ? Wb : Wa;
        if (src) __syncthreads();   // mma of src 0 done reading smem
        // convert fp32 -> bf16 hi/lo into swizzled tiles
        for (int idx = t; idx < 4096; idx += 256) {
            int row = idx >> 5, c4 = (idx & 31) << 2;
            float4 v = *(const float4*)(X + (size_t)(r0 + row) * FF + c4);
            __nv_bfloat16 h0 = __float2bfloat16(v.x), h1 = __float2bfloat16(v.y);
            __nv_bfloat16 h2 = __float2bfloat16(v.z), h3 = __float2bfloat16(v.w);
            uint32_t off = toff(row, c4);
            *(uint2*)(sAh + off) = make_uint2(pk_bf(h0, h1), pk_bf(h2, h3));
            *(uint2*)(sAl + off) = make_uint2(
                pk_bf(__float2bfloat16(v.x - __bfloat162float(h0)), __float2bfloat16(v.y - __bfloat162float(h1))),
                pk_bf(__float2bfloat16(v.z - __bfloat162float(h2)), __float2bfloat16(v.w - __bfloat162float(h3))));
        }
        for (int idx = t; idx < 4096; idx += 256) {
            int row = idx >> 5, c4 = (idx & 31) << 2;
            float4 v = *(const float4*)(W + (size_t)row * FF + c4);
            __nv_bfloat16 h0 = __float2bfloat16(v.x), h1 = __float2bfloat16(v.y);
            __nv_bfloat16 h2 = __float2bfloat16(v.z), h3 = __float2bfloat16(v.w);
            uint32_t off = toff(row, c4);
            *(uint2*)(sBh + off) = make_uint2(pk_bf(h0, h1), pk_bf(h2, h3));
            *(uint2*)(sBl + off) = make_uint2(
                pk_bf(__float2bfloat16(v.x - __bfloat162float(h0)), __float2bfloat16(v.y - __bfloat162float(h1))),
                pk_bf(__float2bfloat16(v.z - __bfloat162float(h2)), __float2bfloat16(v.w - __bfloat162float(h3))));
        }
        __syncthreads();

        for (int pass = 0; pass < 3; pass++) {
            const uint32_t baseA = aA + (pass == 2 ? 32768u : 0u);
            const uint32_t baseB = aB + (pass == 1 ? 32768u : 0u);
            const uint32_t rowA0 = baseA + (uint32_t)arow * 256;
            const uint32_t rowA1 = baseA + (uint32_t)(arow + 16) * 256;
            const uint32_t rowB0 = baseB + (uint32_t)brow * 256;
#pragma unroll
            for (int ks = 0; ks < 8; ks++) {
                uint32_t a[2][4], bfr[4][4];
                uint32_t ua = (uint32_t)(((ks * 2 + aku) ^ ar7) << 4);
                ldm_x4(a[0], rowA0 + ua);
                ldm_x4(a[1], rowA1 + ua);
                uint32_t ub = (uint32_t)(((ks * 2 + bku) ^ br7) << 4);
#pragma unroll
                for (int nc = 0; nc < 4; nc++)
                    ldm_x4(bfr[nc], rowB0 + (uint32_t)nc * 16 * 256 + ub);
#pragma unroll
                for (int mt = 0; mt < 2; mt++)
#pragma unroll
                    for (int nf = 0; nf < 8; nf++)
                        mma16816(c[mt][nf], a[mt], &bfr[nf >> 1][(nf & 1) * 2]);
            }
        }
    }

    // epilogue: bias + activation, direct stores
    const int l4 = lane >> 2, l2 = (lane & 3) * 2;
#pragma unroll
    for (int mt = 0; mt < 2; mt++) {
        int row = r0 + wm * 32 + mt * 16 + l4;
#pragma unroll
        for (int nf = 0; nf < 8; nf++) {
            int col = wn * 64 + nf * 8 + l2;
            float b0 = bias[col], b1 = bias[col + 1];
            float v0 = c[mt][nf][0] + b0, v1 = c[mt][nf][1] + b1;
            float v2 = c[mt][nf][2] + b0, v3 = c[mt][nf][3] + b1;
            if (RELU) {
                v0 = fmaxf(v0, 0.f); v1 = fmaxf(v1, 0.f);
                v2 = fmaxf(v2, 0.f); v3 = fmaxf(v3, 0.f);
            }
            *(float2*)(out + (size_t)row * FF + col) = make_float2(v0, v1);
            *(float2*)(out + (size_t)(row + 8) * FF + col) = make_float2(v2, v3);
        }
    }
}

// ---------------- launch ----------------
extern "C" void kernel_launch(void* const* d_in, const int* in_sizes, int n_in,
                              void* d_out, int out_size) {
    const float* x   = (const float*)d_in[0];
    const float* W1l = (const float*)d_in[1];
    const float* b1l = (const float*)d_in[2];
    const float* W1r = (const float*)d_in[3];
    const float* W2l = (const float*)d_in[4];
    const float* b2l = (const float*)d_in[5];
    const float* W2r = (const float*)d_in[6];
    float* out = (float*)d_out;

    void* aptr = nullptr;
    cudaGetSymbolAddress(&aptr, g_Abits);
    float* mp = nullptr; cudaGetSymbolAddress((void**)&mp, g_m);
    float* hp = nullptr; cudaGetSymbolAddress((void**)&hp, g_h);

    cudaFuncSetAttribute(knn_kernel, cudaFuncAttributeMaxDynamicSharedMemorySize, KNN_SMEM);
    cudaFuncSetAttribute(mma_gemm<true>,  cudaFuncAttributeMaxDynamicSharedMemorySize, MMA_SMEM);
    cudaFuncSetAttribute(mma_gemm<false>, cudaFuncAttributeMaxDynamicSharedMemorySize, MMA_SMEM);

    cudaMemsetAsync(aptr, 0, (size_t)BN * 16 * sizeof(unsigned int), 0);
    sq_kernel<<<BN / 4, 128>>>(x);
    dim3 kg(7, BB);
    knn_kernel<<<kg, 256, KNN_SMEM>>>(x);
    agg_kernel<<<BN / 4, 128>>>(x, mp);
    mma_gemm<true><<<BN / 128, 256, MMA_SMEM>>>(mp, W1l, x, W1r, b1l, hp);
    agg_kernel<<<BN / 4, 128>>>(hp, mp);
    mma_gemm<false><<<BN / 128, 256, MMA_SMEM>>>(mp, W2l, hp, W2r, b2l, out);
}